// round 9
// baseline (speedup 1.0000x reference)
#include <cuda_runtime.h>

#define BATCH 32
#define IN_H  128
#define IN_W  512
#define CHAN  32
#define OUT_H 64
#define OUT_W 256

// Block = 256 threads, covers 64 output points: 32 consecutive wx for
// (b, hy_base) and (b, hy_base+32).
// Phase 1: threads 0..63 compute per-point weights + pixel indices -> smem.
// Phase 2: all 256 threads (8 per point, float4 channel group each) gather
//          4 pixels and blend, reading params via LDS broadcast.
// Stores use __stcg to keep output writes out of L1's wavefront queue.
// Grid = 8 wx-tiles * 32 hy_base * 32 b = 8192 blocks.

struct PParam {
    float    wA, wB, wC, wD;
    unsigned iA, iB, iC, iD;   // pixel index * 8 (float4 units), without cg
};

__global__ void __launch_bounds__(256, 8)
stn_bilinear_kernel(const float* __restrict__ image,
                    const float* __restrict__ theta,
                    float* __restrict__ out)
{
    __shared__ PParam sp[64];

    const unsigned tid = threadIdx.x;
    const unsigned bid = blockIdx.x;
    const unsigned wx_base = (bid & 7u) << 5;      // 8 tiles of 32
    const unsigned r       = bid >> 3;
    const unsigned hy_base = r & 31u;              // 0..31
    const unsigned b       = r >> 5;               // 0..31

    // ---- Phase 1: 64 threads compute params for the block's 64 points ----
    if (tid < 64u) {
        const unsigned p  = tid;
        const unsigned wx = wx_base + (p & 31u);
        const unsigned hy = hy_base + ((p >> 5) << 5);   // +0 or +32

        const float xg = (float)wx * (2.0f / 255.0f) - 1.0f;
        const float yg = (float)hy * (2.0f / 63.0f) - 1.0f;

        // theta[b] 2x3; reference hack: zero row 1 of batch 0, row 0 of batch 1
        const float* th = theta + b * 6u;
        float t00 = __ldg(th + 0), t01 = __ldg(th + 1), t02 = __ldg(th + 2);
        float t10 = __ldg(th + 3), t11 = __ldg(th + 4), t12 = __ldg(th + 5);
        if (b == 0u) { t10 = 0.0f; t11 = 0.0f; t12 = 0.0f; }
        if (b == 1u) { t00 = 0.0f; t01 = 0.0f; t02 = 0.0f; }

        float cx = t00 * xg + t01 * yg + t02;
        float cy = t10 * xg + t11 * yg + t12;

        float x = 0.5f * (cx + 1.0f) * (float)IN_W;   // uses W, not W-1
        float y = 0.5f * (cy + 1.0f) * (float)IN_H;

        int x0 = (int)x;                              // trunc toward zero
        int y0 = (int)y;
        int x1 = x0 + 1;
        int y1 = y0 + 1;
        x0 = min(max(x0, 0), IN_W - 1);               // clip BEFORE weights
        x1 = min(max(x1, 0), IN_W - 1);
        y0 = min(max(y0, 0), IN_H - 1);
        y1 = min(max(y1, 0), IN_H - 1);

        float x0f = (float)x0, x1f = (float)x1;
        float y0f = (float)y0, y1f = (float)y1;

        PParam pp;
        pp.wA = (x1f - x) * (y1f - y);
        pp.wB = (x1f - x) * (y - y0f);
        pp.wC = (x - x0f) * (y1f - y);
        pp.wD = (x - x0f) * (y - y0f);

        const unsigned basePix = b * (unsigned)(IN_H * IN_W);
        const unsigned row0 = basePix + (unsigned)y0 * (unsigned)IN_W;
        const unsigned row1 = basePix + (unsigned)y1 * (unsigned)IN_W;
        pp.iA = (row0 + (unsigned)x0) << 3;
        pp.iB = (row1 + (unsigned)x0) << 3;
        pp.iC = (row0 + (unsigned)x1) << 3;
        pp.iD = (row1 + (unsigned)x1) << 3;

        sp[p] = pp;
    }
    __syncthreads();

    // ---- Phase 2: 8 threads per point, 2 points per thread ----
    const unsigned cg = tid & 7u;
    const unsigned p0 = tid >> 3;        // 0..31  (point at hy_base)
    // second point: p0 + 32               (point at hy_base+32)

    const float4* __restrict__ img4 = (const float4*)image;
    float4* __restrict__ out4 = (float4*)out;

    const unsigned wx = wx_base + (p0 & 31u);
    const unsigned oBase = ((b * (unsigned)OUT_H + hy_base) * (unsigned)OUT_W + wx) * 8u + cg;

    #pragma unroll
    for (int half = 0; half < 2; ++half) {
        const PParam pp = sp[p0 + (unsigned)half * 32u];

        float4 pA = __ldg(img4 + (pp.iA + cg));
        float4 pB = __ldg(img4 + (pp.iB + cg));
        float4 pC = __ldg(img4 + (pp.iC + cg));
        float4 pD = __ldg(img4 + (pp.iD + cg));

        float4 res;
        res.x = pA.x * pp.wA + pB.x * pp.wB + pC.x * pp.wC + pD.x * pp.wD;
        res.y = pA.y * pp.wA + pB.y * pp.wB + pC.y * pp.wC + pD.y * pp.wD;
        res.z = pA.z * pp.wA + pB.z * pp.wB + pC.z * pp.wC + pD.z * pp.wD;
        res.w = pA.w * pp.wA + pB.w * pp.wB + pC.w * pp.wC + pD.w * pp.wD;

        __stcg(&out4[oBase + (unsigned)half * (32u * OUT_W * 8u)], res);
    }
}

extern "C" void kernel_launch(void* const* d_in, const int* in_sizes, int n_in,
                              void* d_out, int out_size)
{
    const float* image = (const float*)d_in[0];
    const float* theta = (const float*)d_in[1];
    float*       out   = (float*)d_out;

    stn_bilinear_kernel<<<8192, 256>>>(image, theta, out);
}